// round 1
// baseline (speedup 1.0000x reference)
#include <cuda_runtime.h>

#define B_ 32
#define N_ 4096
#define DU_ 64
#define D_ 128

// Scratch (allocation-free rule: __device__ globals)
__device__ float g_wt[2][128];      // w~_h = Wk[:,h-slice] @ q_h
__device__ float g_c[2];            // q_h . bk_h
__device__ float g_m[32][2][128];   // sum_n alpha * z
__device__ float g_abar[32][2];     // sum_n alpha

__device__ __forceinline__ float fast_tanh(float y) {
    // tanh(y) = 1 - 2/(exp(2y)+1); saturates correctly at +/-inf
    float e = __expf(2.0f * y);
    return 1.0f - 2.0f / (e + 1.0f);
}

__device__ __forceinline__ float gelu_tanh(float x) {
    const float k0 = 0.7978845608028654f; // sqrt(2/pi)
    float inner = k0 * (x + 0.044715f * x * x * x);
    return 0.5f * x * (1.0f + fast_tanh(inner));
}

// ---------------------------------------------------------------------------
// Kernel A: compute q, w~, c; zero accumulators. 1 block x 256 threads.
// ---------------------------------------------------------------------------
__global__ void setup_kernel(const float* __restrict__ embed,
                             const float* __restrict__ Wq, const float* __restrict__ bq,
                             const float* __restrict__ Wk, const float* __restrict__ bk) {
    __shared__ float qs[128];
    int tid = threadIdx.x;
    if (tid < 128) {
        float s = bq[tid];
        #pragma unroll 8
        for (int i = 0; i < 128; i++) s += embed[i] * Wq[i * 128 + tid];
        qs[tid] = s;
    }
    __syncthreads();
    {
        int h = tid >> 7, i = tid & 127;
        float s = 0.f;
        #pragma unroll 8
        for (int d = 0; d < 64; d++) s += Wk[i * 128 + h * 64 + d] * qs[h * 64 + d];
        g_wt[h][i] = s;
    }
    if (tid < 2) {
        float s = 0.f;
        for (int d = 0; d < 64; d++) s += bk[tid * 64 + d] * qs[tid * 64 + d];
        g_c[tid] = s;
    }
    float* gm = &g_m[0][0][0];
    for (int i = tid; i < 32 * 2 * 128; i += 256) gm[i] = 0.f;
    if (tid < 64) (&g_abar[0][0])[tid] = 0.f;
}

// ---------------------------------------------------------------------------
// Kernel B: fused MLP + alpha + moment accumulation.
// grid = (N/64, B), 256 threads. 64 rows per block.
// ---------------------------------------------------------------------------
__global__ __launch_bounds__(256, 1)
void main_kernel(const float* __restrict__ u,
                 const float* __restrict__ W1, const float* __restrict__ b1,
                 const float* __restrict__ W2, const float* __restrict__ b2) {
    extern __shared__ float sm[];
    float* sW1 = sm;                  // 64*128
    float* sW2 = sW1 + 64 * 128;      // 128*128
    float* sU  = sW2 + 128 * 128;     // 64*68 (padded)
    float* sZ1 = sU  + 64 * 68;       // 64*132 (padded)
    float* sWT = sZ1 + 64 * 132;      // 256
    float* sM  = sWT + 256;           // 256
    float* sA  = sM  + 256;           // 2

    int tid = threadIdx.x;
    int b = blockIdx.y;
    int row0 = blockIdx.x * 64;

    sM[tid] = 0.f;
    if (tid < 2) sA[tid] = 0.f;

    // stage weights + w~ into SMEM
    {
        const float4* dW1 = (const float4*)W1;
        float4* sW1v = (float4*)sW1;
        #pragma unroll
        for (int i = tid; i < 64 * 128 / 4; i += 256) sW1v[i] = dW1[i];
        const float4* dW2 = (const float4*)W2;
        float4* sW2v = (float4*)sW2;
        #pragma unroll
        for (int i = tid; i < 128 * 128 / 4; i += 256) sW2v[i] = dW2[i];
        sWT[tid] = (&g_wt[0][0])[tid];
    }
    // stage u tile: row = tid/4, each thread copies 4 float4
    {
        int r = tid >> 2, q = tid & 3;
        const float4* src = (const float4*)(u + ((size_t)b * N_ + row0 + r) * DU_);
        float4* dst = (float4*)(sU + r * 68);
        #pragma unroll
        for (int i = 0; i < 4; i++) dst[q * 4 + i] = src[q * 4 + i];
    }
    __syncthreads();

    int tr = tid >> 4;   // 0..15 (row group)
    int tc = tid & 15;   // 0..15 (col group)
    int r0 = tr * 4;
    int c0 = tc * 8;

    float acc[4][8];

    // ---- Stage 1: Z1 = gelu(U @ W1 + b1), K=64 ----
    #pragma unroll
    for (int i = 0; i < 4; i++)
        #pragma unroll
        for (int j = 0; j < 8; j++) acc[i][j] = 0.f;

    #pragma unroll 8
    for (int k = 0; k < 64; k++) {
        float av[4];
        #pragma unroll
        for (int i = 0; i < 4; i++) av[i] = sU[(r0 + i) * 68 + k];
        float4 w0 = *(const float4*)&sW1[k * 128 + c0];
        float4 w1 = *(const float4*)&sW1[k * 128 + c0 + 4];
        float wv[8] = {w0.x, w0.y, w0.z, w0.w, w1.x, w1.y, w1.z, w1.w};
        #pragma unroll
        for (int i = 0; i < 4; i++)
            #pragma unroll
            for (int j = 0; j < 8; j++) acc[i][j] += av[i] * wv[j];
    }
    #pragma unroll
    for (int j = 0; j < 8; j++) {
        float bb = b1[c0 + j];
        #pragma unroll
        for (int i = 0; i < 4; i++)
            sZ1[(r0 + i) * 132 + c0 + j] = gelu_tanh(acc[i][j] + bb);
    }
    __syncthreads();

    // ---- Stage 2: Z2 = gelu(Z1 @ W2 + b2), K=128 (kept in registers) ----
    #pragma unroll
    for (int i = 0; i < 4; i++)
        #pragma unroll
        for (int j = 0; j < 8; j++) acc[i][j] = 0.f;

    #pragma unroll 8
    for (int k = 0; k < 128; k++) {
        float av[4];
        #pragma unroll
        for (int i = 0; i < 4; i++) av[i] = sZ1[(r0 + i) * 132 + k];
        float4 w0 = *(const float4*)&sW2[k * 128 + c0];
        float4 w1 = *(const float4*)&sW2[k * 128 + c0 + 4];
        float wv[8] = {w0.x, w0.y, w0.z, w0.w, w1.x, w1.y, w1.z, w1.w};
        #pragma unroll
        for (int i = 0; i < 4; i++)
            #pragma unroll
            for (int j = 0; j < 8; j++) acc[i][j] += av[i] * wv[j];
    }
    float z2[4][8];
    #pragma unroll
    for (int j = 0; j < 8; j++) {
        float bb = b2[c0 + j];
        #pragma unroll
        for (int i = 0; i < 4; i++) z2[i][j] = gelu_tanh(acc[i][j] + bb);
    }

    // ---- Stage 3: alpha + moment accumulation ----
    float wt0[8], wt1[8];
    #pragma unroll
    for (int j = 0; j < 8; j++) { wt0[j] = sWT[c0 + j]; wt1[j] = sWT[128 + c0 + j]; }
    float cc0 = g_c[0], cc1 = g_c[1];

    float mac0[8], mac1[8];
    #pragma unroll
    for (int j = 0; j < 8; j++) { mac0[j] = 0.f; mac1[j] = 0.f; }
    float asum0 = 0.f, asum1 = 0.f;

    #pragma unroll
    for (int i = 0; i < 4; i++) {
        float p0 = 0.f, p1 = 0.f;
        #pragma unroll
        for (int j = 0; j < 8; j++) { p0 += z2[i][j] * wt0[j]; p1 += z2[i][j] * wt1[j]; }
        // row is spread across 16 lanes (tc) inside one half-warp: xor-reduce <16
        #pragma unroll
        for (int s = 1; s < 16; s <<= 1) {
            p0 += __shfl_xor_sync(0xffffffffu, p0, s);
            p1 += __shfl_xor_sync(0xffffffffu, p1, s);
        }
        p0 += cc0; p1 += cc1;
        asum0 += p0; asum1 += p1;
        #pragma unroll
        for (int j = 0; j < 8; j++) { mac0[j] += p0 * z2[i][j]; mac1[j] += p1 * z2[i][j]; }
    }
    #pragma unroll
    for (int j = 0; j < 8; j++) {
        atomicAdd(&sM[c0 + j], mac0[j]);
        atomicAdd(&sM[128 + c0 + j], mac1[j]);
    }
    if (tc == 0) { atomicAdd(&sA[0], asum0); atomicAdd(&sA[1], asum1); }
    __syncthreads();

    // flush block partials to global
    atomicAdd(&g_m[b][0][0] + tid, sM[tid]);
    if (tid < 2) atomicAdd(&g_abar[b][tid], sA[tid]);
}

// ---------------------------------------------------------------------------
// Kernel C: tiny epilogue. grid = B blocks x 128 threads.
// ---------------------------------------------------------------------------
__global__ void epilogue_kernel(const float* __restrict__ Wv, const float* __restrict__ bv,
                                const float* __restrict__ Wo, const float* __restrict__ bo,
                                float* __restrict__ out) {
    __shared__ float ov[128];
    int b = blockIdx.x;
    int j = threadIdx.x;
    int h = j >> 6;
    const float invN = 1.0f / (float)N_;

    float s = g_abar[b][h] * bv[j];
    const float* mm = &g_m[b][h][0];
    #pragma unroll 8
    for (int p = 0; p < 128; p++) s += mm[p] * Wv[p * 128 + j];
    ov[j] = s * invN;
    __syncthreads();

    float o = bo[j];
    #pragma unroll 8
    for (int p = 0; p < 128; p++) o += ov[p] * Wo[p * 128 + j];
    out[b * 128 + j] = o;
}

// ---------------------------------------------------------------------------
extern "C" void kernel_launch(void* const* d_in, const int* in_sizes, int n_in,
                              void* d_out, int out_size) {
    const float* u     = (const float*)d_in[0];
    // d_in[1] = x : unused by the reference
    const float* W1    = (const float*)d_in[2];
    const float* b1    = (const float*)d_in[3];
    const float* W2    = (const float*)d_in[4];
    const float* b2    = (const float*)d_in[5];
    const float* embed = (const float*)d_in[6];
    const float* Wq    = (const float*)d_in[7];
    const float* bq    = (const float*)d_in[8];
    const float* Wk    = (const float*)d_in[9];
    const float* bk    = (const float*)d_in[10];
    const float* Wv    = (const float*)d_in[11];
    const float* bv    = (const float*)d_in[12];
    const float* Wo    = (const float*)d_in[13];
    const float* bo    = (const float*)d_in[14];
    float* out = (float*)d_out;

    const size_t smem_bytes =
        (size_t)(64 * 128 + 128 * 128 + 64 * 68 + 64 * 132 + 256 + 256 + 8) * sizeof(float);
    cudaFuncSetAttribute(main_kernel, cudaFuncAttributeMaxDynamicSharedMemorySize,
                         (int)smem_bytes);

    setup_kernel<<<1, 256>>>(embed, Wq, bq, Wk, bk);
    dim3 grid(N_ / 64, B_);
    main_kernel<<<grid, 256, smem_bytes>>>(u, W1, b1, W2, b2);
    epilogue_kernel<<<B_, 128>>>(Wv, bv, Wo, bo, out);
}

// round 2
// speedup vs baseline: 2.1661x; 2.1661x over previous
#include <cuda_runtime.h>

#define B_ 32
#define N_ 4096
#define DU_ 64
#define D_ 128

// Scratch (allocation-free rule: __device__ globals)
__device__ float g_wt[2][128];      // w~_h = Wk[:,h-slice] @ q_h
__device__ float g_c[2];            // q_h . bk_h
__device__ float g_m[32][2][128];   // sum_n alpha * z
__device__ float g_abar[32][2];     // sum_n alpha

__device__ __forceinline__ float fast_tanh(float y) {
    float e = __expf(2.0f * y);
    return 1.0f - 2.0f / (e + 1.0f);
}

__device__ __forceinline__ float gelu_tanh(float x) {
    const float k0 = 0.7978845608028654f; // sqrt(2/pi)
    float inner = k0 * (x + 0.044715f * x * x * x);
    return 0.5f * x * (1.0f + fast_tanh(inner));
}

__device__ __forceinline__ unsigned f2tf32(float x) {
    unsigned y;
    asm("cvt.rna.tf32.f32 %0, %1;" : "=r"(y) : "f"(x));
    return y;
}

__device__ __forceinline__ void mma8(float* c, const unsigned* a, unsigned b0, unsigned b1) {
    asm volatile(
        "mma.sync.aligned.m16n8k8.row.col.f32.tf32.tf32.f32 "
        "{%0,%1,%2,%3}, {%4,%5,%6,%7}, {%8,%9}, {%0,%1,%2,%3};\n"
        : "+f"(c[0]), "+f"(c[1]), "+f"(c[2]), "+f"(c[3])
        : "r"(a[0]), "r"(a[1]), "r"(a[2]), "r"(a[3]), "r"(b0), "r"(b1));
}

// ---------------------------------------------------------------------------
// Kernel A: compute q, w~, c; zero accumulators. 1 block x 256 threads.
// ---------------------------------------------------------------------------
__global__ void setup_kernel(const float* __restrict__ embed,
                             const float* __restrict__ Wq, const float* __restrict__ bq,
                             const float* __restrict__ Wk, const float* __restrict__ bk) {
    __shared__ float qs[128];
    int tid = threadIdx.x;
    if (tid < 128) {
        float s = bq[tid];
        #pragma unroll 8
        for (int i = 0; i < 128; i++) s += embed[i] * Wq[i * 128 + tid];
        qs[tid] = s;
    }
    __syncthreads();
    {
        int h = tid >> 7, i = tid & 127;
        float s = 0.f;
        #pragma unroll 8
        for (int d = 0; d < 64; d++) s += Wk[i * 128 + h * 64 + d] * qs[h * 64 + d];
        g_wt[h][i] = s;
    }
    if (tid < 2) {
        float s = 0.f;
        for (int d = 0; d < 64; d++) s += bk[tid * 64 + d] * qs[tid * 64 + d];
        g_c[tid] = s;
    }
    float* gm = &g_m[0][0][0];
    for (int i = tid; i < 32 * 2 * 128; i += 256) gm[i] = 0.f;
    if (tid < 64) (&g_abar[0][0])[tid] = 0.f;
}

// ---------------------------------------------------------------------------
// Kernel B: fused MLP (tf32 tensor cores) + alpha + moment accumulation.
// grid = (N/128, B), 256 threads = 8 warps. 128 rows per block.
// Warp tiling: warp (wm in 0..3, wn in 0..1) owns rows [wm*32,+32), cols [wn*64,+64).
//
// SMEM strides: A-operands stride = 4 (mod 32)  -> conflict-free frag loads
//               B-operands stride = 8 (mod 32)  -> conflict-free frag loads
// ---------------------------------------------------------------------------
#define OFF_U   0        // 128 x 68  (A, tf32)
#define OFF_W1  8704     // 64  x 136 (B, tf32)
#define OFF_Z1  17408    // 128 x 132 (A, tf32)
#define OFF_W2  34304    // 128 x 136 (B, tf32)
#define OFF_WT  51712    // 256
#define OFF_AL  51968    // 256
#define SMEM_FLOATS 52224
// sZ2 aliases [0, 16512) over sU+sW1 (dead after stage 1): 128 x 129 fp32

__global__ __launch_bounds__(256, 1)
void main_kernel(const float* __restrict__ u,
                 const float* __restrict__ W1, const float* __restrict__ b1,
                 const float* __restrict__ W2, const float* __restrict__ b2) {
    extern __shared__ float sm[];
    float* sU  = sm + OFF_U;
    float* sW1 = sm + OFF_W1;
    float* sZ1 = sm + OFF_Z1;
    float* sW2 = sm + OFF_W2;
    float* sWT = sm + OFF_WT;
    float* sAl = sm + OFF_AL;
    float* sZ2 = sm;  // alias

    const int tid = threadIdx.x;
    const int b = blockIdx.y;
    const int row0 = blockIdx.x * 128;

    // ---- stage inputs into SMEM (with tf32 rounding) ----
    {   // u tile: 128 x 64 -> 2048 float4
        const float4* src = (const float4*)(u + ((size_t)b * N_ + row0) * DU_);
        #pragma unroll
        for (int it = 0; it < 8; it++) {
            int i = tid + it * 256;
            int r = i >> 4, c4 = i & 15;
            float4 v = src[i];
            float* d = &sU[r * 68 + c4 * 4];
            d[0] = __uint_as_float(f2tf32(v.x));
            d[1] = __uint_as_float(f2tf32(v.y));
            d[2] = __uint_as_float(f2tf32(v.z));
            d[3] = __uint_as_float(f2tf32(v.w));
        }
    }
    {   // W1: 64 x 128 -> stride 136
        const float4* src = (const float4*)W1;
        #pragma unroll
        for (int it = 0; it < 8; it++) {
            int i = tid + it * 256;
            int r = i >> 5, c4 = i & 31;
            float4 v = src[i];
            float* d = &sW1[r * 136 + c4 * 4];
            d[0] = __uint_as_float(f2tf32(v.x));
            d[1] = __uint_as_float(f2tf32(v.y));
            d[2] = __uint_as_float(f2tf32(v.z));
            d[3] = __uint_as_float(f2tf32(v.w));
        }
    }
    {   // W2: 128 x 128 -> stride 136
        const float4* src = (const float4*)W2;
        #pragma unroll
        for (int it = 0; it < 16; it++) {
            int i = tid + it * 256;
            int r = i >> 5, c4 = i & 31;
            float4 v = src[i];
            float* d = &sW2[r * 136 + c4 * 4];
            d[0] = __uint_as_float(f2tf32(v.x));
            d[1] = __uint_as_float(f2tf32(v.y));
            d[2] = __uint_as_float(f2tf32(v.z));
            d[3] = __uint_as_float(f2tf32(v.w));
        }
    }
    sWT[tid] = (&g_wt[0][0])[tid];
    __syncthreads();

    const int lane = tid & 31, warp = tid >> 5;
    const int wm = warp & 3, wn = warp >> 2;
    const int g = lane >> 2, t = lane & 3;

    float acc[2][8][4];

    // ================= Stage 1: Z1 = gelu(U @ W1 + b1), K = 64 =================
    #pragma unroll
    for (int mt = 0; mt < 2; mt++)
        #pragma unroll
        for (int nt = 0; nt < 8; nt++)
            #pragma unroll
            for (int e = 0; e < 4; e++) acc[mt][nt][e] = 0.f;

    #pragma unroll
    for (int k0 = 0; k0 < 64; k0 += 8) {
        unsigned a[2][4];
        #pragma unroll
        for (int mt = 0; mt < 2; mt++) {
            int r = wm * 32 + mt * 16 + g;
            a[mt][0] = __float_as_uint(sU[r * 68 + k0 + t]);
            a[mt][1] = __float_as_uint(sU[(r + 8) * 68 + k0 + t]);
            a[mt][2] = __float_as_uint(sU[r * 68 + k0 + t + 4]);
            a[mt][3] = __float_as_uint(sU[(r + 8) * 68 + k0 + t + 4]);
        }
        #pragma unroll
        for (int nt = 0; nt < 8; nt++) {
            int n = wn * 64 + nt * 8 + g;
            unsigned b0 = __float_as_uint(sW1[(k0 + t) * 136 + n]);
            unsigned bb = __float_as_uint(sW1[(k0 + t + 4) * 136 + n]);
            mma8(acc[0][nt], a[0], b0, bb);
            mma8(acc[1][nt], a[1], b0, bb);
        }
    }
    #pragma unroll
    for (int nt = 0; nt < 8; nt++) {
        int c0 = wn * 64 + nt * 8 + 2 * t;
        float bc0 = __ldg(&b1[c0]), bc1 = __ldg(&b1[c0 + 1]);
        #pragma unroll
        for (int mt = 0; mt < 2; mt++) {
            int r = wm * 32 + mt * 16 + g;
            sZ1[r * 132 + c0]           = __uint_as_float(f2tf32(gelu_tanh(acc[mt][nt][0] + bc0)));
            sZ1[r * 132 + c0 + 1]       = __uint_as_float(f2tf32(gelu_tanh(acc[mt][nt][1] + bc1)));
            sZ1[(r + 8) * 132 + c0]     = __uint_as_float(f2tf32(gelu_tanh(acc[mt][nt][2] + bc0)));
            sZ1[(r + 8) * 132 + c0 + 1] = __uint_as_float(f2tf32(gelu_tanh(acc[mt][nt][3] + bc1)));
        }
    }
    __syncthreads();

    // ================= Stage 2: Z2 = gelu(Z1 @ W2 + b2), K = 128 =================
    #pragma unroll
    for (int mt = 0; mt < 2; mt++)
        #pragma unroll
        for (int nt = 0; nt < 8; nt++)
            #pragma unroll
            for (int e = 0; e < 4; e++) acc[mt][nt][e] = 0.f;

    #pragma unroll
    for (int k0 = 0; k0 < 128; k0 += 8) {
        unsigned a[2][4];
        #pragma unroll
        for (int mt = 0; mt < 2; mt++) {
            int r = wm * 32 + mt * 16 + g;
            a[mt][0] = __float_as_uint(sZ1[r * 132 + k0 + t]);
            a[mt][1] = __float_as_uint(sZ1[(r + 8) * 132 + k0 + t]);
            a[mt][2] = __float_as_uint(sZ1[r * 132 + k0 + t + 4]);
            a[mt][3] = __float_as_uint(sZ1[(r + 8) * 132 + k0 + t + 4]);
        }
        #pragma unroll
        for (int nt = 0; nt < 8; nt++) {
            int n = wn * 64 + nt * 8 + g;
            unsigned b0 = __float_as_uint(sW2[(k0 + t) * 136 + n]);
            unsigned bb = __float_as_uint(sW2[(k0 + t + 4) * 136 + n]);
            mma8(acc[0][nt], a[0], b0, bb);
            mma8(acc[1][nt], a[1], b0, bb);
        }
    }
    // z2 in fp32 to sZ2 (stride 129; aliases dead sU/sW1 region)
    #pragma unroll
    for (int nt = 0; nt < 8; nt++) {
        int c0 = wn * 64 + nt * 8 + 2 * t;
        float bc0 = __ldg(&b2[c0]), bc1 = __ldg(&b2[c0 + 1]);
        #pragma unroll
        for (int mt = 0; mt < 2; mt++) {
            int r = wm * 32 + mt * 16 + g;
            sZ2[r * 129 + c0]           = gelu_tanh(acc[mt][nt][0] + bc0);
            sZ2[r * 129 + c0 + 1]       = gelu_tanh(acc[mt][nt][1] + bc1);
            sZ2[(r + 8) * 129 + c0]     = gelu_tanh(acc[mt][nt][2] + bc0);
            sZ2[(r + 8) * 129 + c0 + 1] = gelu_tanh(acc[mt][nt][3] + bc1);
        }
    }
    __syncthreads();

    // ================= Stage 3: alpha + moments (fp32) =================
    {
        int r = tid & 127, h = tid >> 7;
        const float* wt = &sWT[h * 128];
        float a = g_c[h];
        #pragma unroll 8
        for (int j = 0; j < 128; j++) a += sZ2[r * 129 + j] * wt[j];
        sAl[h * 128 + r] = a;
    }
    __syncthreads();
    {
        int j = tid & 127, h = tid >> 7;
        const float* al = &sAl[h * 128];
        float m = 0.f;
        #pragma unroll 8
        for (int r = 0; r < 128; r++) m += al[r] * sZ2[r * 129 + j];
        atomicAdd(&g_m[b][h][j], m);
        if (tid < 2) {
            float s = 0.f;
            #pragma unroll 8
            for (int r = 0; r < 128; r++) s += sAl[tid * 128 + r];
            atomicAdd(&g_abar[b][tid], s);
        }
    }
}

// ---------------------------------------------------------------------------
// Kernel C: tiny epilogue. grid = B blocks x 128 threads.
// ---------------------------------------------------------------------------
__global__ void epilogue_kernel(const float* __restrict__ Wv, const float* __restrict__ bv,
                                const float* __restrict__ Wo, const float* __restrict__ bo,
                                float* __restrict__ out) {
    __shared__ float ov[128];
    int b = blockIdx.x;
    int j = threadIdx.x;
    int h = j >> 6;
    const float invN = 1.0f / (float)N_;

    float s = g_abar[b][h] * bv[j];
    const float* mm = &g_m[b][h][0];
    #pragma unroll 8
    for (int p = 0; p < 128; p++) s += mm[p] * Wv[p * 128 + j];
    ov[j] = s * invN;
    __syncthreads();

    float o = bo[j];
    #pragma unroll 8
    for (int p = 0; p < 128; p++) o += ov[p] * Wo[p * 128 + j];
    out[b * 128 + j] = o;
}

// ---------------------------------------------------------------------------
extern "C" void kernel_launch(void* const* d_in, const int* in_sizes, int n_in,
                              void* d_out, int out_size) {
    const float* u     = (const float*)d_in[0];
    // d_in[1] = x : unused by the reference
    const float* W1    = (const float*)d_in[2];
    const float* b1    = (const float*)d_in[3];
    const float* W2    = (const float*)d_in[4];
    const float* b2    = (const float*)d_in[5];
    const float* embed = (const float*)d_in[6];
    const float* Wq    = (const float*)d_in[7];
    const float* bq    = (const float*)d_in[8];
    const float* Wk    = (const float*)d_in[9];
    const float* bk    = (const float*)d_in[10];
    const float* Wv    = (const float*)d_in[11];
    const float* bv    = (const float*)d_in[12];
    const float* Wo    = (const float*)d_in[13];
    const float* bo    = (const float*)d_in[14];
    float* out = (float*)d_out;

    const size_t smem_bytes = (size_t)SMEM_FLOATS * sizeof(float);  // 208,896 B
    cudaFuncSetAttribute(main_kernel, cudaFuncAttributeMaxDynamicSharedMemorySize,
                         (int)smem_bytes);

    setup_kernel<<<1, 256>>>(embed, Wq, bq, Wk, bk);
    dim3 grid(N_ / 128, B_);
    main_kernel<<<grid, 256, smem_bytes>>>(u, W1, b1, W2, b2);
    epilogue_kernel<<<B_, 128>>>(Wv, bv, Wo, bo, out);
}